// round 10
// baseline (speedup 1.0000x reference)
#include <cuda_runtime.h>

#define N_NODES 100000
#define N_EDGES 1600000
#define D 64
#define CAP 64   // max bucket capacity per dst; deg ~ Poisson(16), P(>64) ~ 1e-18

// Scratch (device globals — no allocation allowed in kernel_launch)
__device__ int g_cursor[N_NODES];                          // per-dst edge count
__device__ __align__(16) uint2 g_buckets[N_NODES * CAP];   // packed {src, w_bits}, 51.2 MB

// ---------------------------------------------------------------------------
// Kernel 1: zero the cursors
// ---------------------------------------------------------------------------
__global__ void init_kernel() {
    int i = blockIdx.x * blockDim.x + threadIdx.x;
    if (i < N_NODES) g_cursor[i] = 0;
}

// ---------------------------------------------------------------------------
// Kernel 2: bucket fill. One thread per edge: claim a slot in dst's bucket,
// store packed (src, edge_weight). Int atomics spread over 100k addresses.
// ---------------------------------------------------------------------------
__global__ void fill_kernel(const int* __restrict__ src,
                            const int* __restrict__ dst,
                            const float* __restrict__ ew) {
    int e = blockIdx.x * blockDim.x + threadIdx.x;
    if (e >= N_EDGES) return;
    int d = __ldg(dst + e);
    int p = atomicAdd(g_cursor + d, 1);
    if (p < CAP) {
        uint2 rec;
        rec.x = (unsigned)__ldg(src + e);
        rec.y = __float_as_uint(__ldg(ew + e));
        g_buckets[(size_t)d * CAP + p] = rec;
    }
}

// ---------------------------------------------------------------------------
// Kernel 3: fused aggregate + mean + dual GEMV + bias.
// One warp per node. Phase A: lane l accumulates dims {2l, 2l+1} over the
// node's bucket (coalesced 256B feat gathers, uniform 8B record broadcast).
// Phase B: neighbor mean spilled to smem, then GEMV with k-major smem weights:
//   sW[kq*64 + j] = float4(W[j][4kq..4kq+3])
// lane l computes outputs j = l and j = 32+l -> consecutive float4s, LDS.128
// conflict-free. Inputs broadcast from smem/global.
// ---------------------------------------------------------------------------
__global__ void __launch_bounds__(256) agg_kernel(
        const float2* __restrict__ featv2,
        const float4* __restrict__ featv4,
        const float* __restrict__ W_neigh,
        const float* __restrict__ W_self,
        const float* __restrict__ bias,
        float* __restrict__ out) {
    __shared__ float4 sWs[16 * 64];     // 16 KB
    __shared__ float4 sWn[16 * 64];     // 16 KB
    __shared__ float  sNeigh[8][64];    // 2 KB, one row per warp

    // Stage weights, transposed to k-major quads
    for (int i = threadIdx.x; i < 16 * 64; i += blockDim.x) {
        sWs[i] = reinterpret_cast<const float4*>(W_self )[(i & 63) * 16 + (i >> 6)];
        sWn[i] = reinterpret_cast<const float4*>(W_neigh)[(i & 63) * 16 + (i >> 6)];
    }
    __syncthreads();

    const int warp = threadIdx.x >> 5;
    const int l    = threadIdx.x & 31;

    int node = blockIdx.x * 8 + warp;
    if (node >= N_NODES) return;

    // ---- Phase A: weighted neighbor sum, lane owns dims 2l, 2l+1 ----
    int deg = g_cursor[node];            // uniform per warp
    int cnt = min(deg, CAP);
    const uint2* ep = g_buckets + (size_t)node * CAP;

    float2 acc = make_float2(0.f, 0.f);
    #pragma unroll 4
    for (int e = 0; e < cnt; ++e) {
        uint2 rec = __ldg(ep + e);                       // uniform -> broadcast
        float w = __uint_as_float(rec.y);
        float2 f = __ldg(featv2 + (size_t)rec.x * 32 + l); // coalesced 256B
        acc.x += f.x * w;
        acc.y += f.y * w;
    }
    float invd = 1.0f / fmaxf((float)deg, 1.0f);
    sNeigh[warp][2 * l]     = acc.x * invd;
    sNeigh[warp][2 * l + 1] = acc.y * invd;
    __syncwarp();

    // ---- Phase B: dual GEMV ----
    const float4* fv  = featv4 + (size_t)node * 16;
    const float4* nbv = reinterpret_cast<const float4*>(sNeigh[warp]);

    float o0 = 0.f, o1 = 0.f;
    #pragma unroll
    for (int kq = 0; kq < 16; ++kq) {
        float4 f  = __ldg(fv + kq);      // uniform -> broadcast, L1/L2 hit
        float4 nb = nbv[kq];             // smem broadcast

        float4 ws = sWs[kq * 64 + l];
        float4 wn = sWn[kq * 64 + l];
        o0 += f.x * ws.x + f.y * ws.y + f.z * ws.z + f.w * ws.w
            + nb.x * wn.x + nb.y * wn.y + nb.z * wn.z + nb.w * wn.w;

        ws = sWs[kq * 64 + 32 + l];
        wn = sWn[kq * 64 + 32 + l];
        o1 += f.x * ws.x + f.y * ws.y + f.z * ws.z + f.w * ws.w
            + nb.x * wn.x + nb.y * wn.y + nb.z * wn.z + nb.w * wn.w;
    }

    float* o = out + (size_t)node * D;
    o[l]      = o0 + __ldg(bias + l);
    o[32 + l] = o1 + __ldg(bias + 32 + l);
}

// ---------------------------------------------------------------------------
extern "C" void kernel_launch(void* const* d_in, const int* in_sizes, int n_in,
                              void* d_out, int out_size) {
    const float* feat = (const float*)d_in[0];
    const int*   src  = (const int*)d_in[1];    // int32 (JAX x64 disabled)
    const int*   dst  = (const int*)d_in[2];
    const float* ew   = (const float*)d_in[3];
    const float* Wn   = (const float*)d_in[4];
    const float* Ws   = (const float*)d_in[5];
    const float* bias = (const float*)d_in[6];
    float*       out  = (float*)d_out;

    init_kernel<<<(N_NODES + 255) / 256, 256>>>();

    fill_kernel<<<(N_EDGES + 255) / 256, 256>>>(src, dst, ew);

    // One warp per node, 8 nodes per 256-thread block
    agg_kernel<<<(N_NODES + 7) / 8, 256>>>(
        (const float2*)feat, (const float4*)feat, Wn, Ws, bias, out);
}

// round 11
// speedup vs baseline: 1.1428x; 1.1428x over previous
#include <cuda_runtime.h>

#define N_NODES 100000
#define N_EDGES 1600000
#define D 64

// Scratch (device globals — no allocation allowed in kernel_launch)
__device__ __align__(16) float g_accum[N_NODES * D];  // 25.6 MB weighted sums per dst
__device__ float g_deg[N_NODES];                      // in-degree per dst

// ---------------------------------------------------------------------------
// Kernel 1: zero the accumulators (graph replays reuse the globals)
// ---------------------------------------------------------------------------
__global__ void zero_kernel() {
    int i = blockIdx.x * blockDim.x + threadIdx.x;
    float4* a = reinterpret_cast<float4*>(g_accum);
    const int n4 = (N_NODES * D) / 4;   // 1.6M float4
    if (i < n4) a[i] = make_float4(0.f, 0.f, 0.f, 0.f);
    if (i < N_NODES) g_deg[i] = 0.f;
}

// ---------------------------------------------------------------------------
// Kernel 2: edge scatter (unchanged from the 242us baseline).
// 8 threads per edge, 2x float4 gather + 2x red.global.add.v4.f32 each.
// ---------------------------------------------------------------------------
__global__ void edge_kernel(const float4* __restrict__ featv,
                            const int* __restrict__ src,
                            const int* __restrict__ dst,
                            const float* __restrict__ ew) {
    int t = blockIdx.x * blockDim.x + threadIdx.x;
    int e = t >> 3;
    if (e >= N_EDGES) return;
    int p = t & 7;

    int   s = __ldg(src + e);
    int   d = __ldg(dst + e);
    float w = __ldg(ew + e);

    float4 f0 = __ldg(featv + (size_t)s * 16 + p * 2);
    float4 f1 = __ldg(featv + (size_t)s * 16 + p * 2 + 1);

    float* base = g_accum + (size_t)d * D + p * 8;
    asm volatile("red.global.add.v4.f32 [%0], {%1, %2, %3, %4};"
                 :: "l"(base), "f"(f0.x * w), "f"(f0.y * w), "f"(f0.z * w), "f"(f0.w * w)
                 : "memory");
    asm volatile("red.global.add.v4.f32 [%0], {%1, %2, %3, %4};"
                 :: "l"(base + 4), "f"(f1.x * w), "f"(f1.y * w), "f"(f1.z * w), "f"(f1.w * w)
                 : "memory");
    if (p == 0) {
        atomicAdd(g_deg + d, 1.0f);
    }
}

// ---------------------------------------------------------------------------
// Kernel 3: per-node mean + dual GEMV + bias, weight-amortized.
// Warp owns 8 consecutive nodes; lane l owns outputs j=l and j=32+l.
// Per kq, the 4 weight float4s are loaded ONCE from smem and applied to all
// 8 nodes -> smem traffic 4KB/node (was 32KB/node, the old bottleneck).
// Inputs are warp-uniform LDG.128 broadcasts (L1-resident).
// N_NODES = 100000 = 12500 groups of 8 exactly -> no guards needed.
// ---------------------------------------------------------------------------
__global__ void __launch_bounds__(256) node_kernel(
        const float4* __restrict__ featv,
        const float* __restrict__ W_neigh,
        const float* __restrict__ W_self,
        const float* __restrict__ bias,
        float* __restrict__ out) {
    __shared__ float4 sWs[16 * 64];   // W_self,  k-major: sW[kq*64 + j]
    __shared__ float4 sWn[16 * 64];   // W_neigh

    for (int i = threadIdx.x; i < 16 * 64; i += blockDim.x) {
        int j  = i & 63;
        int kq = i >> 6;
        sWs[i] = reinterpret_cast<const float4*>(W_self )[j * 16 + kq];
        sWn[i] = reinterpret_cast<const float4*>(W_neigh)[j * 16 + kq];
    }
    __syncthreads();

    const int warp = threadIdx.x >> 5;
    const int l    = threadIdx.x & 31;
    const int group = blockIdx.x * 8 + warp;     // 8 warps/block
    if (group >= N_NODES / 8) return;
    const int node0 = group * 8;

    const float4* accv = reinterpret_cast<const float4*>(g_accum);

    // Per-node inverse degree (uniform loads, L2-hit)
    float invd[8];
    #pragma unroll
    for (int i = 0; i < 8; ++i)
        invd[i] = 1.0f / fmaxf(g_deg[node0 + i], 1.0f);

    float accA[8], accB[8];
    #pragma unroll
    for (int i = 0; i < 8; ++i) { accA[i] = 0.f; accB[i] = 0.f; }

    #pragma unroll
    for (int kq = 0; kq < 16; ++kq) {
        // 4 weight vectors per warp per kq, reused across 8 nodes
        float4 ws0 = sWs[kq * 64 + l];
        float4 wn0 = sWn[kq * 64 + l];
        float4 ws1 = sWs[kq * 64 + 32 + l];
        float4 wn1 = sWn[kq * 64 + 32 + l];

        #pragma unroll
        for (int i = 0; i < 8; ++i) {
            const size_t off = (size_t)(node0 + i) * 16 + kq;
            float4 f  = __ldg(featv + off);   // uniform -> broadcast
            float4 nb = accv[off];
            float id = invd[i];
            float nx = nb.x * id, ny = nb.y * id, nz = nb.z * id, nw = nb.w * id;

            accA[i] += f.x * ws0.x + f.y * ws0.y + f.z * ws0.z + f.w * ws0.w
                     + nx * wn0.x + ny * wn0.y + nz * wn0.z + nw * wn0.w;
            accB[i] += f.x * ws1.x + f.y * ws1.y + f.z * ws1.z + f.w * ws1.w
                     + nx * wn1.x + ny * wn1.y + nz * wn1.z + nw * wn1.w;
        }
    }

    float b0 = __ldg(bias + l);
    float b1 = __ldg(bias + 32 + l);
    #pragma unroll
    for (int i = 0; i < 8; ++i) {
        float* o = out + (size_t)(node0 + i) * D;
        o[l]      = accA[i] + b0;
        o[32 + l] = accB[i] + b1;
    }
}

// ---------------------------------------------------------------------------
extern "C" void kernel_launch(void* const* d_in, const int* in_sizes, int n_in,
                              void* d_out, int out_size) {
    const float* feat = (const float*)d_in[0];
    const int*   src  = (const int*)d_in[1];    // int32 (JAX x64 disabled)
    const int*   dst  = (const int*)d_in[2];
    const float* ew   = (const float*)d_in[3];
    const float* Wn   = (const float*)d_in[4];
    const float* Ws   = (const float*)d_in[5];
    const float* bias = (const float*)d_in[6];
    float*       out  = (float*)d_out;

    zero_kernel<<<6250, 256>>>();

    edge_kernel<<<(N_EDGES * 8 + 255) / 256, 256>>>(
        (const float4*)feat, src, dst, ew);

    // 8 nodes/warp, 8 warps/block -> 64 nodes/block, 12500 groups total
    node_kernel<<<(N_NODES / 8 + 7) / 8, 256>>>(
        (const float4*)feat, Wn, Ws, bias, out);
}

// round 12
// speedup vs baseline: 1.4787x; 1.2939x over previous
#include <cuda_runtime.h>

#define N_NODES 100000
#define N_EDGES 1600000
#define D 64
#define CAP 64   // deg ~ Poisson(16); P(deg>64) astronomically small

// Scratch (device globals — no allocation allowed in kernel_launch)
__device__ int g_cursor[N_NODES];                         // per-dst edge count
__device__ __align__(16) uint2 g_buckets[N_NODES * CAP];  // packed {src, w_bits}
__device__ __align__(16) float g_accum[N_NODES * D];      // neighbor MEAN per node
__device__ float g_deg[N_NODES];

// ---------------------------------------------------------------------------
// Kernel 1: zero cursors
// ---------------------------------------------------------------------------
__global__ void init_kernel() {
    int i = blockIdx.x * blockDim.x + threadIdx.x;
    if (i < N_NODES) g_cursor[i] = 0;
}

// ---------------------------------------------------------------------------
// Kernel 2: bucket fill. One thread per edge; int atomic spread over 100k
// addresses, one scattered 8B record write.
// ---------------------------------------------------------------------------
__global__ void fill_kernel(const int* __restrict__ src,
                            const int* __restrict__ dst,
                            const float* __restrict__ ew) {
    int e = blockIdx.x * blockDim.x + threadIdx.x;
    if (e >= N_EDGES) return;
    int d = __ldg(dst + e);
    int p = atomicAdd(g_cursor + d, 1);
    if (p < CAP) {
        uint2 rec;
        rec.x = (unsigned)__ldg(src + e);
        rec.y = __float_as_uint(__ldg(ew + e));
        g_buckets[(size_t)d * CAP + p] = rec;
    }
}

// ---------------------------------------------------------------------------
// Kernel 3: gather-mean. One warp per node.
// Records fetched 32-at-a-time by the lanes (one coalesced 256B load), then
// shfl-broadcast so every feat gather address is register-resident ->
// independent LDGs, high MLP. Lane l owns dims {2l, 2l+1}.
// Writes the MEAN into g_accum (no zero pass needed; deg=0 -> zeros).
// ---------------------------------------------------------------------------
__global__ void __launch_bounds__(256) gather_kernel(
        const float2* __restrict__ featv2) {
    int gw = (blockIdx.x * blockDim.x + threadIdx.x) >> 5;  // warp id = node
    int l = threadIdx.x & 31;
    if (gw >= N_NODES) return;
    const int node = gw;

    int deg = g_cursor[node];
    int cnt = min(deg, CAP);
    const uint2* ep = g_buckets + (size_t)node * CAP;

    float2 acc = make_float2(0.f, 0.f);

    for (int base = 0; base < cnt; base += 32) {
        int m = min(cnt - base, 32);
        uint2 rec = (l < m) ? __ldg(ep + base + l) : make_uint2(0u, 0u);

        if (m == 32) {
            #pragma unroll
            for (int j = 0; j < 32; ++j) {
                unsigned s = __shfl_sync(0xffffffffu, rec.x, j);
                float    w = __uint_as_float(__shfl_sync(0xffffffffu, rec.y, j));
                float2   f = __ldg(featv2 + (size_t)s * 32 + l);
                acc.x += f.x * w;
                acc.y += f.y * w;
            }
        } else {
            #pragma unroll 4
            for (int j = 0; j < m; ++j) {
                unsigned s = __shfl_sync(0xffffffffu, rec.x, j);
                float    w = __uint_as_float(__shfl_sync(0xffffffffu, rec.y, j));
                float2   f = __ldg(featv2 + (size_t)s * 32 + l);
                acc.x += f.x * w;
                acc.y += f.y * w;
            }
        }
    }

    float invd = 1.0f / fmaxf((float)deg, 1.0f);
    reinterpret_cast<float2*>(g_accum)[(size_t)node * 32 + l] =
        make_float2(acc.x * invd, acc.y * invd);
    if (l == 0) g_deg[node] = 1.0f;   // mean already applied; node kernel divides by max(deg,1)=1
}

// ---------------------------------------------------------------------------
// Kernel 4: per-node dual GEMV + bias (R7's proven version; g_accum already
// holds the mean, g_deg=1 so invd=1).
// Block = 256 threads = 16 nodes, 16 threads/node, 4 outputs each.
// ---------------------------------------------------------------------------
__global__ void node_kernel(const float4* __restrict__ featv,
                            const float* __restrict__ W_neigh,
                            const float* __restrict__ W_self,
                            const float* __restrict__ bias,
                            float* __restrict__ out) {
    __shared__ float4 sWs[16 * 64];
    __shared__ float4 sWn[16 * 64];

    for (int i = threadIdx.x; i < 16 * 64; i += blockDim.x) {
        int j  = i & 63;
        int kq = i >> 6;
        sWs[i] = reinterpret_cast<const float4*>(W_self )[j * 16 + kq];
        sWn[i] = reinterpret_cast<const float4*>(W_neigh)[j * 16 + kq];
    }
    __syncthreads();

    const int jq = threadIdx.x & 15;
    const float4* accv = reinterpret_cast<const float4*>(g_accum);

    for (int base = blockIdx.x * 16; base < N_NODES; base += gridDim.x * 16) {
        int node = base + (threadIdx.x >> 4);
        if (node >= N_NODES) continue;

        const float4* fv = featv + (size_t)node * 16;
        const float4* av = accv + (size_t)node * 16;

        float acc0 = 0.f, acc1 = 0.f, acc2 = 0.f, acc3 = 0.f;

        #pragma unroll
        for (int kq = 0; kq < 16; ++kq) {
            float4 f  = __ldg(fv + kq);
            float4 nb = av[kq];

            float4 ws, wn;
            ws = sWs[kq * 64 + 0 * 16 + jq];
            wn = sWn[kq * 64 + 0 * 16 + jq];
            acc0 += f.x * ws.x + f.y * ws.y + f.z * ws.z + f.w * ws.w
                  + nb.x * wn.x + nb.y * wn.y + nb.z * wn.z + nb.w * wn.w;
            ws = sWs[kq * 64 + 1 * 16 + jq];
            wn = sWn[kq * 64 + 1 * 16 + jq];
            acc1 += f.x * ws.x + f.y * ws.y + f.z * ws.z + f.w * ws.w
                  + nb.x * wn.x + nb.y * wn.y + nb.z * wn.z + nb.w * wn.w;
            ws = sWs[kq * 64 + 2 * 16 + jq];
            wn = sWn[kq * 64 + 2 * 16 + jq];
            acc2 += f.x * ws.x + f.y * ws.y + f.z * ws.z + f.w * ws.w
                  + nb.x * wn.x + nb.y * wn.y + nb.z * wn.z + nb.w * wn.w;
            ws = sWs[kq * 64 + 3 * 16 + jq];
            wn = sWn[kq * 64 + 3 * 16 + jq];
            acc3 += f.x * ws.x + f.y * ws.y + f.z * ws.z + f.w * ws.w
                  + nb.x * wn.x + nb.y * wn.y + nb.z * wn.z + nb.w * wn.w;
        }

        float* o = out + (size_t)node * D;
        o[0 * 16 + jq] = acc0 + __ldg(bias + 0 * 16 + jq);
        o[1 * 16 + jq] = acc1 + __ldg(bias + 1 * 16 + jq);
        o[2 * 16 + jq] = acc2 + __ldg(bias + 2 * 16 + jq);
        o[3 * 16 + jq] = acc3 + __ldg(bias + 3 * 16 + jq);
    }
}

// ---------------------------------------------------------------------------
extern "C" void kernel_launch(void* const* d_in, const int* in_sizes, int n_in,
                              void* d_out, int out_size) {
    const float* feat = (const float*)d_in[0];
    const int*   src  = (const int*)d_in[1];    // int32 (JAX x64 disabled)
    const int*   dst  = (const int*)d_in[2];
    const float* ew   = (const float*)d_in[3];
    const float* Wn   = (const float*)d_in[4];
    const float* Ws   = (const float*)d_in[5];
    const float* bias = (const float*)d_in[6];
    float*       out  = (float*)d_out;

    init_kernel<<<(N_NODES + 255) / 256, 256>>>();

    fill_kernel<<<(N_EDGES + 255) / 256, 256>>>(src, dst, ew);

    // one warp per node: 100000 warps -> 12500 blocks of 256
    gather_kernel<<<12500, 256>>>((const float2*)feat);

    node_kernel<<<1480, 256>>>((const float4*)feat, Wn, Ws, bias, out);
}

// round 13
// speedup vs baseline: 1.7674x; 1.1952x over previous
#include <cuda_runtime.h>

#define N_NODES 100000
#define N_EDGES 1600000
#define D 64
#define CAP 64   // deg ~ Poisson(16); P(deg>64) astronomically small

// Scratch (device globals — no allocation allowed in kernel_launch)
__device__ int g_cursor[N_NODES];                         // per-dst edge count
__device__ __align__(16) uint2 g_buckets[N_NODES * CAP];  // packed {src, w_bits}
__device__ __align__(16) float g_accum[N_NODES * D];      // neighbor MEAN per node

// ---------------------------------------------------------------------------
// Kernel 1: zero cursors
// ---------------------------------------------------------------------------
__global__ void init_kernel() {
    int i = blockIdx.x * blockDim.x + threadIdx.x;
    if (i < N_NODES) g_cursor[i] = 0;
}

// ---------------------------------------------------------------------------
// Kernel 2: bucket fill. One thread per edge; int atomic spread over 100k
// addresses, one scattered 8B record write.
// ---------------------------------------------------------------------------
__global__ void fill_kernel(const int* __restrict__ src,
                            const int* __restrict__ dst,
                            const float* __restrict__ ew) {
    int e = blockIdx.x * blockDim.x + threadIdx.x;
    if (e >= N_EDGES) return;
    int d = __ldg(dst + e);
    int p = atomicAdd(g_cursor + d, 1);
    if (p < CAP) {
        uint2 rec;
        rec.x = (unsigned)__ldg(src + e);
        rec.y = __float_as_uint(__ldg(ew + e));
        g_buckets[(size_t)d * CAP + p] = rec;
    }
}

// ---------------------------------------------------------------------------
// Kernel 3: gather-mean. One warp per node. Records fetched 32-at-a-time by
// the lanes (one coalesced 256B load), shfl-broadcast -> register-resident
// gather addresses, high MLP. Lane l owns dims {2l, 2l+1}. Writes the MEAN.
// ---------------------------------------------------------------------------
__global__ void __launch_bounds__(256) gather_kernel(
        const float2* __restrict__ featv2) {
    int gw = (blockIdx.x * blockDim.x + threadIdx.x) >> 5;  // warp id = node
    int l = threadIdx.x & 31;
    if (gw >= N_NODES) return;
    const int node = gw;

    int deg = g_cursor[node];
    int cnt = min(deg, CAP);
    const uint2* ep = g_buckets + (size_t)node * CAP;

    float2 acc = make_float2(0.f, 0.f);

    for (int base = 0; base < cnt; base += 32) {
        int m = min(cnt - base, 32);
        uint2 rec = (l < m) ? __ldg(ep + base + l) : make_uint2(0u, 0u);

        if (m == 32) {
            #pragma unroll
            for (int j = 0; j < 32; ++j) {
                unsigned s = __shfl_sync(0xffffffffu, rec.x, j);
                float    w = __uint_as_float(__shfl_sync(0xffffffffu, rec.y, j));
                float2   f = __ldg(featv2 + (size_t)s * 32 + l);
                acc.x += f.x * w;
                acc.y += f.y * w;
            }
        } else {
            #pragma unroll 4
            for (int j = 0; j < m; ++j) {
                unsigned s = __shfl_sync(0xffffffffu, rec.x, j);
                float    w = __uint_as_float(__shfl_sync(0xffffffffu, rec.y, j));
                float2   f = __ldg(featv2 + (size_t)s * 32 + l);
                acc.x += f.x * w;
                acc.y += f.y * w;
            }
        }
    }

    float invd = 1.0f / fmaxf((float)deg, 1.0f);
    reinterpret_cast<float2*>(g_accum)[(size_t)node * 32 + l] =
        make_float2(acc.x * invd, acc.y * invd);
}

// ---------------------------------------------------------------------------
// Kernel 4: dual GEMV + bias, LDS amortized over 4 nodes per thread.
// Block = 256 = 16 slots x 16 jq. Thread (slot, jq) handles nodes
//   base + slot + 16*i, i = 0..3  (64 nodes per block),
// so a node's 16 jq-lanes stay contiguous -> f/nb loads are warp-broadcast
// LDG.128 and the 16 lanes read 16 consecutive weight float4s (LDS.128,
// conflict-free). Each 8-LDS group per kq now feeds 4 nodes instead of 1:
// smem phase cost drops ~4x (this was 92% L1TEX at 125us).
// ---------------------------------------------------------------------------
__global__ void __launch_bounds__(256) node_kernel(
        const float4* __restrict__ featv,
        const float* __restrict__ W_neigh,
        const float* __restrict__ W_self,
        const float* __restrict__ bias,
        float* __restrict__ out) {
    __shared__ float4 sWs[16 * 64];   // k-major: sW[kq*64 + j]
    __shared__ float4 sWn[16 * 64];

    for (int i = threadIdx.x; i < 16 * 64; i += blockDim.x) {
        int j  = i & 63;
        int kq = i >> 6;
        sWs[i] = reinterpret_cast<const float4*>(W_self )[j * 16 + kq];
        sWn[i] = reinterpret_cast<const float4*>(W_neigh)[j * 16 + kq];
    }
    __syncthreads();

    const int jq   = threadIdx.x & 15;
    const int slot = threadIdx.x >> 4;
    const int base = blockIdx.x * 64;

    const float4* accv = reinterpret_cast<const float4*>(g_accum);

    int   nodes[4];
    bool  ok[4];
    #pragma unroll
    for (int i = 0; i < 4; ++i) {
        nodes[i] = base + slot + 16 * i;
        ok[i] = nodes[i] < N_NODES;
    }

    float acc[4][4];
    #pragma unroll
    for (int i = 0; i < 4; ++i)
        #pragma unroll
        for (int jj = 0; jj < 4; ++jj) acc[i][jj] = 0.f;

    #pragma unroll 4
    for (int kq = 0; kq < 16; ++kq) {
        // 8 weight vectors, loaded once, reused for 4 nodes
        float4 ws0 = sWs[kq * 64 + 0 * 16 + jq];
        float4 ws1 = sWs[kq * 64 + 1 * 16 + jq];
        float4 ws2 = sWs[kq * 64 + 2 * 16 + jq];
        float4 ws3 = sWs[kq * 64 + 3 * 16 + jq];
        float4 wn0 = sWn[kq * 64 + 0 * 16 + jq];
        float4 wn1 = sWn[kq * 64 + 1 * 16 + jq];
        float4 wn2 = sWn[kq * 64 + 2 * 16 + jq];
        float4 wn3 = sWn[kq * 64 + 3 * 16 + jq];

        #pragma unroll
        for (int i = 0; i < 4; ++i) {
            if (!ok[i]) continue;
            const size_t off = (size_t)nodes[i] * 16 + kq;
            float4 f  = __ldg(featv + off);   // broadcast among node's 16 lanes
            float4 nb = accv[off];

            acc[i][0] += f.x * ws0.x + f.y * ws0.y + f.z * ws0.z + f.w * ws0.w
                       + nb.x * wn0.x + nb.y * wn0.y + nb.z * wn0.z + nb.w * wn0.w;
            acc[i][1] += f.x * ws1.x + f.y * ws1.y + f.z * ws1.z + f.w * ws1.w
                       + nb.x * wn1.x + nb.y * wn1.y + nb.z * wn1.z + nb.w * wn1.w;
            acc[i][2] += f.x * ws2.x + f.y * ws2.y + f.z * ws2.z + f.w * ws2.w
                       + nb.x * wn2.x + nb.y * wn2.y + nb.z * wn2.z + nb.w * wn2.w;
            acc[i][3] += f.x * ws3.x + f.y * ws3.y + f.z * ws3.z + f.w * ws3.w
                       + nb.x * wn3.x + nb.y * wn3.y + nb.z * wn3.z + nb.w * wn3.w;
        }
    }

    float b0 = __ldg(bias + 0 * 16 + jq);
    float b1 = __ldg(bias + 1 * 16 + jq);
    float b2 = __ldg(bias + 2 * 16 + jq);
    float b3 = __ldg(bias + 3 * 16 + jq);

    #pragma unroll
    for (int i = 0; i < 4; ++i) {
        if (!ok[i]) continue;
        float* o = out + (size_t)nodes[i] * D;
        o[0 * 16 + jq] = acc[i][0] + b0;
        o[1 * 16 + jq] = acc[i][1] + b1;
        o[2 * 16 + jq] = acc[i][2] + b2;
        o[3 * 16 + jq] = acc[i][3] + b3;
    }
}

// ---------------------------------------------------------------------------
extern "C" void kernel_launch(void* const* d_in, const int* in_sizes, int n_in,
                              void* d_out, int out_size) {
    const float* feat = (const float*)d_in[0];
    const int*   src  = (const int*)d_in[1];    // int32 (JAX x64 disabled)
    const int*   dst  = (const int*)d_in[2];
    const float* ew   = (const float*)d_in[3];
    const float* Wn   = (const float*)d_in[4];
    const float* Ws   = (const float*)d_in[5];
    const float* bias = (const float*)d_in[6];
    float*       out  = (float*)d_out;

    init_kernel<<<(N_NODES + 255) / 256, 256>>>();

    fill_kernel<<<(N_EDGES + 255) / 256, 256>>>(src, dst, ew);

    // one warp per node: 100000 warps -> 12500 blocks of 256
    gather_kernel<<<12500, 256>>>((const float2*)feat);

    // 64 nodes per block
    node_kernel<<<(N_NODES + 63) / 64, 256>>>(
        (const float4*)feat, Wn, Ws, bias, out);
}

// round 14
// speedup vs baseline: 2.6365x; 1.4918x over previous
#include <cuda_runtime.h>
#include <cstdint>

#define N_NODES 100000
#define N_EDGES 1600000
#define D 64
#define CAP 64   // deg ~ Poisson(16); P(deg>64) astronomically small

// Scratch (device globals — no allocation allowed in kernel_launch)
__device__ int g_cursor[N_NODES];                         // per-dst edge count
__device__ __align__(16) uint2 g_buckets[N_NODES * CAP];  // packed {src, w_bits}
__device__ __align__(16) float g_accum[N_NODES * D];      // neighbor MEAN per node

// ---------------------------------------------------------------------------
// Kernel 1: zero cursors
// ---------------------------------------------------------------------------
__global__ void init_kernel() {
    int i = blockIdx.x * blockDim.x + threadIdx.x;
    if (i < N_NODES) g_cursor[i] = 0;
}

// ---------------------------------------------------------------------------
// Kernel 2: bucket fill (unchanged)
// ---------------------------------------------------------------------------
__global__ void fill_kernel(const int* __restrict__ src,
                            const int* __restrict__ dst,
                            const float* __restrict__ ew) {
    int e = blockIdx.x * blockDim.x + threadIdx.x;
    if (e >= N_EDGES) return;
    int d = __ldg(dst + e);
    int p = atomicAdd(g_cursor + d, 1);
    if (p < CAP) {
        uint2 rec;
        rec.x = (unsigned)__ldg(src + e);
        rec.y = __float_as_uint(__ldg(ew + e));
        g_buckets[(size_t)d * CAP + p] = rec;
    }
}

// ---------------------------------------------------------------------------
// Kernel 3: gather-mean, one warp per node (unchanged)
// ---------------------------------------------------------------------------
__global__ void __launch_bounds__(256) gather_kernel(
        const float2* __restrict__ featv2) {
    int gw = (blockIdx.x * blockDim.x + threadIdx.x) >> 5;
    int l = threadIdx.x & 31;
    if (gw >= N_NODES) return;
    const int node = gw;

    int deg = g_cursor[node];
    int cnt = min(deg, CAP);
    const uint2* ep = g_buckets + (size_t)node * CAP;

    float2 acc = make_float2(0.f, 0.f);

    for (int base = 0; base < cnt; base += 32) {
        int m = min(cnt - base, 32);
        uint2 rec = (l < m) ? __ldg(ep + base + l) : make_uint2(0u, 0u);

        if (m == 32) {
            #pragma unroll
            for (int j = 0; j < 32; ++j) {
                unsigned s = __shfl_sync(0xffffffffu, rec.x, j);
                float    w = __uint_as_float(__shfl_sync(0xffffffffu, rec.y, j));
                float2   f = __ldg(featv2 + (size_t)s * 32 + l);
                acc.x += f.x * w;
                acc.y += f.y * w;
            }
        } else {
            #pragma unroll 4
            for (int j = 0; j < m; ++j) {
                unsigned s = __shfl_sync(0xffffffffu, rec.x, j);
                float    w = __uint_as_float(__shfl_sync(0xffffffffu, rec.y, j));
                float2   f = __ldg(featv2 + (size_t)s * 32 + l);
                acc.x += f.x * w;
                acc.y += f.y * w;
            }
        }
    }

    float invd = 1.0f / fmaxf((float)deg, 1.0f);
    reinterpret_cast<float2*>(g_accum)[(size_t)node * 32 + l] =
        make_float2(acc.x * invd, acc.y * invd);
}

// ---------------------------------------------------------------------------
// Kernel 4: tensor-core GEMM. C[100000,64] = A[100000,128] * W2^T + bias,
// A = [feat || neigh_mean] read directly from the two source arrays,
// W2 = [W_self || W_neigh], tf32-rounded in smem, row pitch 132 floats
// (bank index = 4*g + t + const -> conflict-free 4B LDS for B fragments).
// Warp: 16 nodes x 64 outputs via mma.sync.m16n8k8.tf32 (16 K-steps x 8
// N-frags = 128 MMAs). Block: 8 warps = 128 nodes. fp32 accumulate.
// ---------------------------------------------------------------------------
#define WPITCH 132

__global__ void __launch_bounds__(256) node_mma_kernel(
        const float* __restrict__ feat,
        const float* __restrict__ W_neigh,
        const float* __restrict__ W_self,
        const float* __restrict__ bias,
        float* __restrict__ out) {
    __shared__ float sW[64 * WPITCH];   // 33 KB

    // Stage + tf32-round both weight matrices
    for (int i = threadIdx.x; i < 64 * 64; i += 256) {
        int n = i >> 6, k = i & 63;
        uint32_t ts, tn;
        asm("cvt.rna.tf32.f32 %0, %1;" : "=r"(ts) : "f"(W_self[i]));
        asm("cvt.rna.tf32.f32 %0, %1;" : "=r"(tn) : "f"(W_neigh[i]));
        sW[n * WPITCH + k]      = __uint_as_float(ts);
        sW[n * WPITCH + 64 + k] = __uint_as_float(tn);
    }
    __syncthreads();

    const int warp = threadIdx.x >> 5;
    const int lane = threadIdx.x & 31;
    const int g = lane >> 2;      // group id (row within frag)
    const int t = lane & 3;       // thread in group (col within frag)

    const int m0 = blockIdx.x * 128 + warp * 16;
    if (m0 >= N_NODES) return;

    const int r0 = m0 + g;
    const int r1 = m0 + g + 8;
    const int r0c = min(r0, N_NODES - 1);   // clamp loads; stores guarded
    const int r1c = min(r1, N_NODES - 1);

    float c[8][4];
    #pragma unroll
    for (int nf = 0; nf < 8; ++nf)
        #pragma unroll
        for (int q = 0; q < 4; ++q) c[nf][q] = 0.f;

    #pragma unroll
    for (int ks = 0; ks < 16; ++ks) {
        const int k0 = ks * 8;
        const float* Abase = (k0 < 64) ? (feat + k0) : (g_accum + (k0 - 64));

        float f0 = __ldg(Abase + (size_t)r0c * 64 + t);
        float f1 = __ldg(Abase + (size_t)r1c * 64 + t);
        float f2 = __ldg(Abase + (size_t)r0c * 64 + t + 4);
        float f3 = __ldg(Abase + (size_t)r1c * 64 + t + 4);

        uint32_t a0, a1, a2, a3;
        asm("cvt.rna.tf32.f32 %0, %1;" : "=r"(a0) : "f"(f0));
        asm("cvt.rna.tf32.f32 %0, %1;" : "=r"(a1) : "f"(f1));
        asm("cvt.rna.tf32.f32 %0, %1;" : "=r"(a2) : "f"(f2));
        asm("cvt.rna.tf32.f32 %0, %1;" : "=r"(a3) : "f"(f3));

        #pragma unroll
        for (int nf = 0; nf < 8; ++nf) {
            const float* wb = sW + (nf * 8 + g) * WPITCH + k0 + t;
            uint32_t b0 = __float_as_uint(wb[0]);
            uint32_t b1 = __float_as_uint(wb[4]);
            asm volatile(
                "mma.sync.aligned.m16n8k8.row.col.f32.tf32.tf32.f32 "
                "{%0,%1,%2,%3}, {%4,%5,%6,%7}, {%8,%9}, {%0,%1,%2,%3};"
                : "+f"(c[nf][0]), "+f"(c[nf][1]), "+f"(c[nf][2]), "+f"(c[nf][3])
                : "r"(a0), "r"(a1), "r"(a2), "r"(a3), "r"(b0), "r"(b1));
        }
    }

    // Epilogue: bias + store. c0,c1 -> (r0, n0+2t, n0+2t+1); c2,c3 -> r1.
    #pragma unroll
    for (int nf = 0; nf < 8; ++nf) {
        const int n0 = nf * 8 + 2 * t;
        float bx = __ldg(bias + n0);
        float by = __ldg(bias + n0 + 1);
        if (r0 < N_NODES) {
            float2* p = reinterpret_cast<float2*>(out + (size_t)r0 * 64 + n0);
            *p = make_float2(c[nf][0] + bx, c[nf][1] + by);
        }
        if (r1 < N_NODES) {
            float2* p = reinterpret_cast<float2*>(out + (size_t)r1 * 64 + n0);
            *p = make_float2(c[nf][2] + bx, c[nf][3] + by);
        }
    }
}

// ---------------------------------------------------------------------------
extern "C" void kernel_launch(void* const* d_in, const int* in_sizes, int n_in,
                              void* d_out, int out_size) {
    const float* feat = (const float*)d_in[0];
    const int*   src  = (const int*)d_in[1];    // int32 (JAX x64 disabled)
    const int*   dst  = (const int*)d_in[2];
    const float* ew   = (const float*)d_in[3];
    const float* Wn   = (const float*)d_in[4];
    const float* Ws   = (const float*)d_in[5];
    const float* bias = (const float*)d_in[6];
    float*       out  = (float*)d_out;

    init_kernel<<<(N_NODES + 255) / 256, 256>>>();

    fill_kernel<<<(N_EDGES + 255) / 256, 256>>>(src, dst, ew);

    gather_kernel<<<12500, 256>>>((const float2*)feat);

    // 128 nodes per block -> 782 blocks
    node_mma_kernel<<<(N_NODES + 127) / 128, 256>>>(feat, Wn, Ws, bias, out);
}